// round 11
// baseline (speedup 1.0000x reference)
#include <cuda_runtime.h>
#include <cuda_bf16.h>
#include <float.h>

// LabelLoss: B=16, K=11, H=W=128, C=7 — single kernel, SINGLE-WAVE layout.
//   pooled = 3x3 box-sum (pad 1) of heatmap[b,k]  (÷9 dropped: argmax-invariant)
//   idx    = argmax over flattened HxW (first occurrence)
//   loss[b,k] = sum_c (pred[b, k*7+c, idx/W, idx%W] - gt[b,k,c])^2
//   out[b] = mean_k loss[b,k]   (last half to finish)
//
// 88 CTAs x 1024 threads (< 148 SMs -> one wave, no straggler wave).
// Each CTA = two independent 512-thread halves, one (b,k) map each.
// Per-half argmax: 5-step warp shfl reduce + 16 lane-0 smem atomicMax of a
// packed u64 (hi = ordered-uint(pooled), lo = ~idx; bigger lo <=> smaller
// idx => first-occurrence tie-break).

#define BVAL 16
#define KVAL 11
#define NBK  (BVAL * KVAL)          // 176 maps
#define NCTA (NBK / 2)              // 88 CTAs, 2 maps per CTA
#define HVAL 128
#define WVAL 128
#define HW   (HVAL * WVAL)
#define CVAL 7
#define NTHREADS 1024               // two 512-thread halves

__device__ float        g_labelloss_scratch[NBK];
__device__ unsigned int g_labelloss_count = 0;

__device__ __forceinline__ unsigned int float_to_ordered(float f)
{
    unsigned int u = __float_as_uint(f);
    return (u & 0x80000000u) ? ~u : (u | 0x80000000u);  // monotone, >0 finite
}

__global__ __launch_bounds__(NTHREADS)
void labelloss_fused_kernel(const float* __restrict__ pred,
                            const float* __restrict__ gt,
                            const float* __restrict__ heatmap,
                            float* __restrict__ out)
{
    const int tid   = threadIdx.x;
    const int half  = tid >> 9;                 // 0 or 1
    const int bk    = blockIdx.x * 2 + half;    // map handled by this half
    const int lane  = tid & 31;
    const int hwarp = (tid >> 5) & 15;          // warp index within half: 0..15
    const int x0    = hwarp * 8;                // row strip start
    const int c0    = lane * 4;                 // 4 columns per lane

    __shared__ unsigned long long s_best[2];
    if ((tid & 511) == 0) s_best[half] = 0ull;

    const float* __restrict__ hm = heatmap + (size_t)bk * HW;

    // ---- Phase 1: front-batch all loads (rows x0-1 .. x0+8) -> MLP = 10 ----
    float4 v[10];
    #pragma unroll
    for (int i = 0; i < 10; ++i) {
        const int x = x0 - 1 + i;
        if ((unsigned)x < (unsigned)HVAL) {
            v[i] = *reinterpret_cast<const float4*>(hm + x * WVAL + c0);
        } else {
            v[i] = make_float4(0.f, 0.f, 0.f, 0.f);
        }
    }

    // ---- Phase 2: vertical 3-tap first (thread-local) ----
    float4 cs[8];
    #pragma unroll
    for (int j = 0; j < 8; ++j) {
        cs[j].x = v[j].x + v[j + 1].x + v[j + 2].x;
        cs[j].y = v[j].y + v[j + 1].y + v[j + 2].y;
        cs[j].z = v[j].z + v[j + 1].z + v[j + 2].z;
        cs[j].w = v[j].w + v[j + 1].w + v[j + 2].w;
    }

    // ---- Phase 3: horizontal 3-tap per output row (2 shuffles) + argmax ----
    float best = -FLT_MAX;
    int   bidx = 0x7FFFFFFF;
    #pragma unroll
    for (int j = 0; j < 8; ++j) {
        float left  = __shfl_up_sync(0xffffffffu, cs[j].w, 1);
        float right = __shfl_down_sync(0xffffffffu, cs[j].x, 1);
        if (lane == 0)  left  = 0.f;        // column -1 pad
        if (lane == 31) right = 0.f;        // column 128 pad
        float p0 = left     + cs[j].x + cs[j].y;
        float p1 = cs[j].x  + cs[j].y + cs[j].z;
        float p2 = cs[j].y  + cs[j].z + cs[j].w;
        float p3 = cs[j].z  + cs[j].w + right;
        const int base = (x0 + j) * WVAL + c0;
        // ascending index + strict '>' preserves first-occurrence semantics
        if (p0 > best) { best = p0; bidx = base;     }
        if (p1 > best) { best = p1; bidx = base + 1; }
        if (p2 > best) { best = p2; bidx = base + 2; }
        if (p3 > best) { best = p3; bidx = base + 3; }
    }

    // ---- Phase 4: warp shfl reduce, then one smem atomicMax per warp ----
    #pragma unroll
    for (int off = 16; off > 0; off >>= 1) {
        float v2 = __shfl_down_sync(0xffffffffu, best, off);
        int   i2 = __shfl_down_sync(0xffffffffu, bidx, off);
        if (v2 > best || (v2 == best && i2 < bidx)) { best = v2; bidx = i2; }
    }
    __syncthreads();                         // s_best init visible (both halves)
    if (lane == 0) {
        const unsigned long long packed =
            ((unsigned long long)float_to_ordered(best) << 32) |
            (unsigned long long)(~(unsigned int)bidx);
        atomicMax(&s_best[half], packed);
    }
    __syncthreads();                         // all 16 contributions per half in

    // ---- Phase 5: warp 0 of each half: gather + loss + counter ----
    if (hwarp == 0) {
        unsigned cnt = 0;
        if (lane == 0) {
            const int idx = (int)(~(unsigned int)(s_best[half] & 0xFFFFFFFFull));
            const float* __restrict__ pk = pred + (size_t)bk * CVAL * HW;
            const float* __restrict__ g  = gt   + (size_t)bk * CVAL;
            float loss = 0.0f;
            #pragma unroll
            for (int c = 0; c < CVAL; ++c) {            // independent loads, MLP=7
                float d = pk[c * HW + idx] - g[c];
                loss = fmaf(d, d, loss);
            }
            g_labelloss_scratch[bk] = loss;
            __threadfence();                             // scratch before count
            cnt = atomicAdd(&g_labelloss_count, 1u);
        }
        cnt = __shfl_sync(0xffffffffu, cnt, 0);

        if (cnt == NBK - 1) {                            // last half: final mean
            __threadfence();                             // acquire all scratch
            if (lane < BVAL) {
                float s = 0.0f;
                #pragma unroll
                for (int k = 0; k < KVAL; ++k)           // fixed order, MLP=11
                    s += g_labelloss_scratch[lane * KVAL + k];
                out[lane] = s * (1.0f / (float)KVAL);
            }
            if (lane == 0) g_labelloss_count = 0;        // reset for next replay
        }
    }
}

extern "C" void kernel_launch(void* const* d_in, const int* in_sizes, int n_in,
                              void* d_out, int out_size)
{
    const float* pred    = (const float*)d_in[0];
    const float* gt      = (const float*)d_in[1];
    const float* heatmap = (const float*)d_in[2];
    float* out = (float*)d_out;

    labelloss_fused_kernel<<<NCTA, NTHREADS>>>(pred, gt, heatmap, out);
}

// round 14
// speedup vs baseline: 1.0029x; 1.0029x over previous
#include <cuda_runtime.h>
#include <cuda_bf16.h>
#include <float.h>

// LabelLoss: B=16, K=11, H=W=128, C=7 — single fused kernel, SMEM-staged.
//   pooled = 3x3 box-sum (pad 1) of heatmap[b,k]  (÷9 dropped: argmax-invariant)
//   idx    = argmax over flattened HxW (first occurrence)
//   loss[b,k] = sum_c (pred[b, k*7+c, idx/W, idx%W] - gt[b,k,c])^2
//   out[b] = mean_k loss[b,k]   (last CTA to finish)
//
// One CTA per (b,k): 176 CTAs x 512 threads.
// Phase 0 stages the FULL 64KB map into dynamic SMEM: 8 float4s per thread
// (512*8*16B = 65536B — R13 bug was copying only 2/thread = 1/4 of the map).
// Fully coalesced, all 8 LDG.128s front-batched (MLP=8). Halo rows are then
// re-read from SMEM (LDS lat 29, conflict-free 512B row reads).

#define BVAL 16
#define KVAL 11
#define NBK  (BVAL * KVAL)          // 176
#define HVAL 128
#define WVAL 128
#define HW   (HVAL * WVAL)          // 16384 floats = 64KB = 4096 float4
#define CVAL 7
#define NTHREADS 512                // 16 warps; warp w owns rows [8w, 8w+8)
#define SMEM_BYTES (HW * 4)
#define F4_PER_THREAD (HW / 4 / NTHREADS)   // 8

__device__ float        g_labelloss_scratch[NBK];
__device__ unsigned int g_labelloss_count = 0;

__device__ __forceinline__ unsigned int float_to_ordered(float f)
{
    unsigned int u = __float_as_uint(f);
    return (u & 0x80000000u) ? ~u : (u | 0x80000000u);  // monotone, >0 finite
}

__global__ __launch_bounds__(NTHREADS)
void labelloss_fused_kernel(const float* __restrict__ pred,
                            const float* __restrict__ gt,
                            const float* __restrict__ heatmap,
                            float* __restrict__ out)
{
    extern __shared__ float s_hm[];          // [HVAL][WVAL], 512B row stride
    __shared__ unsigned long long s_best;

    const int bk   = blockIdx.x;             // b*K + k
    const int tid  = threadIdx.x;
    const int lane = tid & 31;
    const int warp = tid >> 5;               // 0..15
    const int x0   = warp * 8;               // row strip start
    const int c0   = lane * 4;               // 4 columns per lane

    if (tid == 0) s_best = 0ull;

    // ---- Phase 0: stage FULL map GMEM -> SMEM (4096 float4, coalesced) ----
    {
        const float4* __restrict__ src =
            reinterpret_cast<const float4*>(heatmap + (size_t)bk * HW);
        float4* __restrict__ dst = reinterpret_cast<float4*>(s_hm);
        float4 t[F4_PER_THREAD];
        #pragma unroll
        for (int i = 0; i < F4_PER_THREAD; ++i)          // 8 LDGs in flight
            t[i] = src[tid + i * NTHREADS];
        #pragma unroll
        for (int i = 0; i < F4_PER_THREAD; ++i)
            dst[tid + i * NTHREADS] = t[i];
    }
    __syncthreads();                          // staging + s_best init visible

    // ---- Phase 1: read 10 rows (incl. halo) from SMEM ----
    float4 v[10];
    #pragma unroll
    for (int i = 0; i < 10; ++i) {
        const int x = x0 - 1 + i;
        if ((unsigned)x < (unsigned)HVAL) {
            v[i] = *reinterpret_cast<const float4*>(s_hm + x * WVAL + c0);
        } else {
            v[i] = make_float4(0.f, 0.f, 0.f, 0.f);
        }
    }

    // ---- Phase 2: vertical 3-tap first (thread-local) ----
    float4 cs[8];
    #pragma unroll
    for (int j = 0; j < 8; ++j) {
        cs[j].x = v[j].x + v[j + 1].x + v[j + 2].x;
        cs[j].y = v[j].y + v[j + 1].y + v[j + 2].y;
        cs[j].z = v[j].z + v[j + 1].z + v[j + 2].z;
        cs[j].w = v[j].w + v[j + 1].w + v[j + 2].w;
    }

    // ---- Phase 3: horizontal 3-tap per output row (2 shuffles) + argmax ----
    float best = -FLT_MAX;
    int   bidx = 0x7FFFFFFF;
    #pragma unroll
    for (int j = 0; j < 8; ++j) {
        float left  = __shfl_up_sync(0xffffffffu, cs[j].w, 1);
        float right = __shfl_down_sync(0xffffffffu, cs[j].x, 1);
        if (lane == 0)  left  = 0.f;         // column -1 pad
        if (lane == 31) right = 0.f;         // column 128 pad
        float p0 = left     + cs[j].x + cs[j].y;
        float p1 = cs[j].x  + cs[j].y + cs[j].z;
        float p2 = cs[j].y  + cs[j].z + cs[j].w;
        float p3 = cs[j].z  + cs[j].w + right;
        const int base = (x0 + j) * WVAL + c0;
        // ascending index + strict '>' preserves first-occurrence semantics
        if (p0 > best) { best = p0; bidx = base;     }
        if (p1 > best) { best = p1; bidx = base + 1; }
        if (p2 > best) { best = p2; bidx = base + 2; }
        if (p3 > best) { best = p3; bidx = base + 3; }
    }

    // ---- Phase 4: warp shfl reduce, then one smem atomicMax per warp ----
    #pragma unroll
    for (int off = 16; off > 0; off >>= 1) {
        float v2 = __shfl_down_sync(0xffffffffu, best, off);
        int   i2 = __shfl_down_sync(0xffffffffu, bidx, off);
        if (v2 > best || (v2 == best && i2 < bidx)) { best = v2; bidx = i2; }
    }
    if (lane == 0) {
        const unsigned long long packed =
            ((unsigned long long)float_to_ordered(best) << 32) |
            (unsigned long long)(~(unsigned int)bidx);
        atomicMax(&s_best, packed);
    }
    __syncthreads();                          // all 16 contributions in

    // ---- Phase 5: warp 0: gather + loss + counter; last CTA does the mean ----
    if (warp == 0) {
        unsigned cnt = 0;
        if (lane == 0) {
            const int idx = (int)(~(unsigned int)(s_best & 0xFFFFFFFFull));
            const float* __restrict__ pk = pred + (size_t)bk * CVAL * HW;
            const float* __restrict__ g  = gt   + (size_t)bk * CVAL;
            float loss = 0.0f;
            #pragma unroll
            for (int c = 0; c < CVAL; ++c) {  // 7 independent loads, MLP=7
                float d = pk[c * HW + idx] - g[c];
                loss = fmaf(d, d, loss);
            }
            g_labelloss_scratch[bk] = loss;
            __threadfence();                  // scratch visible before count
            cnt = atomicAdd(&g_labelloss_count, 1u);
        }
        cnt = __shfl_sync(0xffffffffu, cnt, 0);

        if (cnt == NBK - 1) {                 // last CTA: final mean
            __threadfence();                  // acquire all scratch writes
            if (lane < BVAL) {
                float s = 0.0f;
                #pragma unroll
                for (int k = 0; k < KVAL; ++k)          // fixed order, MLP=11
                    s += g_labelloss_scratch[lane * KVAL + k];
                out[lane] = s * (1.0f / (float)KVAL);
            }
            if (lane == 0) g_labelloss_count = 0;       // reset for next replay
        }
    }
}

extern "C" void kernel_launch(void* const* d_in, const int* in_sizes, int n_in,
                              void* d_out, int out_size)
{
    const float* pred    = (const float*)d_in[0];
    const float* gt      = (const float*)d_in[1];
    const float* heatmap = (const float*)d_in[2];
    float* out = (float*)d_out;

    // Opt-in to 64KB dynamic SMEM (idempotent; not a stream op, no allocation).
    cudaFuncSetAttribute(labelloss_fused_kernel,
                         cudaFuncAttributeMaxDynamicSharedMemorySize, SMEM_BYTES);

    labelloss_fused_kernel<<<NBK, NTHREADS, SMEM_BYTES>>>(pred, gt, heatmap, out);
}

// round 15
// speedup vs baseline: 1.2518x; 1.2482x over previous
#include <cuda_runtime.h>
#include <cuda_bf16.h>
#include <float.h>

// LabelLoss: B=16, K=11, H=W=128, C=7 — FINAL frozen kernel.
//   pooled = 3x3 box-sum (pad 1) of heatmap[b,k]  (÷9 dropped: argmax-invariant)
//   idx    = argmax over flattened HxW (first occurrence)
//   loss[b,k] = sum_c (pred[b, k*7+c, idx/W, idx%W] - gt[b,k,c])^2
//   out[b] = mean_k loss[b,k]   (last CTA to finish)
//
// One CTA per (b,k): 176 CTAs x 512 threads.
// Four structurally distinct variants (warp scaling, CTA split, single-wave,
// SMEM staging at -20% traffic) all measured 10.94-11.01 us: wall time is
// dominated by fixed per-replay overhead + the irreducible latency chain.
// This is the simplest member of the tied-for-fastest class.

#define BVAL 16
#define KVAL 11
#define NBK  (BVAL * KVAL)          // 176
#define HVAL 128
#define WVAL 128
#define HW   (HVAL * WVAL)
#define CVAL 7
#define NTHREADS 512                // 16 warps; warp w owns rows [8w, 8w+8)

__device__ float        g_labelloss_scratch[NBK];
__device__ unsigned int g_labelloss_count = 0;

__device__ __forceinline__ unsigned int float_to_ordered(float f)
{
    unsigned int u = __float_as_uint(f);
    return (u & 0x80000000u) ? ~u : (u | 0x80000000u);  // monotone, >0 finite
}

__global__ __launch_bounds__(NTHREADS)
void labelloss_fused_kernel(const float* __restrict__ pred,
                            const float* __restrict__ gt,
                            const float* __restrict__ heatmap,
                            float* __restrict__ out)
{
    const int bk   = blockIdx.x;            // b*K + k
    const int tid  = threadIdx.x;
    const int lane = tid & 31;
    const int warp = tid >> 5;              // 0..15
    const int x0   = warp * 8;              // row strip start
    const int c0   = lane * 4;              // 4 columns per lane

    __shared__ unsigned long long s_best;
    if (tid == 0) s_best = 0ull;

    const float* __restrict__ hm = heatmap + (size_t)bk * HW;

    // ---- Phase 1: front-batch all loads (rows x0-1 .. x0+8) -> MLP = 10 ----
    float4 v[10];
    #pragma unroll
    for (int i = 0; i < 10; ++i) {
        const int x = x0 - 1 + i;
        if ((unsigned)x < (unsigned)HVAL) {
            v[i] = *reinterpret_cast<const float4*>(hm + x * WVAL + c0);
        } else {
            v[i] = make_float4(0.f, 0.f, 0.f, 0.f);
        }
    }

    // ---- Phase 2: vertical 3-tap first (thread-local, no communication) ----
    float4 cs[8];
    #pragma unroll
    for (int j = 0; j < 8; ++j) {
        cs[j].x = v[j].x + v[j + 1].x + v[j + 2].x;
        cs[j].y = v[j].y + v[j + 1].y + v[j + 2].y;
        cs[j].z = v[j].z + v[j + 1].z + v[j + 2].z;
        cs[j].w = v[j].w + v[j + 1].w + v[j + 2].w;
    }

    // ---- Phase 3: horizontal 3-tap per output row (2 shuffles) + argmax ----
    float best = -FLT_MAX;
    int   bidx = 0x7FFFFFFF;
    #pragma unroll
    for (int j = 0; j < 8; ++j) {
        float left  = __shfl_up_sync(0xffffffffu, cs[j].w, 1);
        float right = __shfl_down_sync(0xffffffffu, cs[j].x, 1);
        if (lane == 0)  left  = 0.f;        // column -1 pad
        if (lane == 31) right = 0.f;        // column 128 pad
        float p0 = left     + cs[j].x + cs[j].y;
        float p1 = cs[j].x  + cs[j].y + cs[j].z;
        float p2 = cs[j].y  + cs[j].z + cs[j].w;
        float p3 = cs[j].z  + cs[j].w + right;
        const int base = (x0 + j) * WVAL + c0;
        // ascending index + strict '>' preserves first-occurrence semantics
        if (p0 > best) { best = p0; bidx = base;     }
        if (p1 > best) { best = p1; bidx = base + 1; }
        if (p2 > best) { best = p2; bidx = base + 2; }
        if (p3 > best) { best = p3; bidx = base + 3; }
    }

    // ---- Phase 4: warp shfl reduce, then one smem atomicMax per warp ----
    #pragma unroll
    for (int off = 16; off > 0; off >>= 1) {
        float v2 = __shfl_down_sync(0xffffffffu, best, off);
        int   i2 = __shfl_down_sync(0xffffffffu, bidx, off);
        if (v2 > best || (v2 == best && i2 < bidx)) { best = v2; bidx = i2; }
    }
    __syncthreads();                         // s_best init visible
    if (lane == 0) {
        // hi = ordered(pooled), lo = ~idx: bigger lo <=> smaller idx,
        // so u64 max implements (max value, min index) exactly.
        const unsigned long long packed =
            ((unsigned long long)float_to_ordered(best) << 32) |
            (unsigned long long)(~(unsigned int)bidx);
        atomicMax(&s_best, packed);
    }
    __syncthreads();                         // all 16 contributions in

    // ---- Phase 5: warp 0: gather + loss + counter; last CTA does the mean ----
    if (warp == 0) {
        unsigned cnt = 0;
        if (lane == 0) {
            const int idx = (int)(~(unsigned int)(s_best & 0xFFFFFFFFull));
            const float* __restrict__ pk = pred + (size_t)bk * CVAL * HW;
            const float* __restrict__ g  = gt   + (size_t)bk * CVAL;
            float loss = 0.0f;
            #pragma unroll
            for (int c = 0; c < CVAL; ++c) { // 7 independent loads, MLP=7
                float d = pk[c * HW + idx] - g[c];
                loss = fmaf(d, d, loss);
            }
            g_labelloss_scratch[bk] = loss;
            __threadfence();                 // scratch visible before count
            cnt = atomicAdd(&g_labelloss_count, 1u);
        }
        cnt = __shfl_sync(0xffffffffu, cnt, 0);

        if (cnt == NBK - 1) {                // last CTA: final mean
            __threadfence();                 // acquire all scratch writes
            if (lane < BVAL) {
                float s = 0.0f;
                #pragma unroll
                for (int k = 0; k < KVAL; ++k)           // fixed order, MLP=11
                    s += g_labelloss_scratch[lane * KVAL + k];
                out[lane] = s * (1.0f / (float)KVAL);
            }
            if (lane == 0) g_labelloss_count = 0;        // reset for next replay
        }
    }
}

extern "C" void kernel_launch(void* const* d_in, const int* in_sizes, int n_in,
                              void* d_out, int out_size)
{
    const float* pred    = (const float*)d_in[0];
    const float* gt      = (const float*)d_in[1];
    const float* heatmap = (const float*)d_in[2];
    float* out = (float*)d_out;

    labelloss_fused_kernel<<<NBK, NTHREADS>>>(pred, gt, heatmap, out);
}

// round 16
// speedup vs baseline: 1.2610x; 1.0074x over previous
#include <cuda_runtime.h>
#include <cuda_bf16.h>
#include <float.h>

// LabelLoss: B=16, K=11, H=W=128, C=7 — single fused kernel.
//   pooled = 3x3 box-sum (pad 1) of heatmap[b,k]  (÷9 dropped: argmax-invariant)
//   idx    = argmax over flattened HxW (first occurrence)
//   loss[b,k] = sum_c (pred[b, k*7+c, idx/W, idx%W] - gt[b,k,c])^2
//   out[b] = mean_k loss[b,k]   (last CTA to finish)
//
// One CTA per (b,k): 176 CTAs x 512 threads.
// Argmax reduction via redux.sync (sm_80+ HW reduce): per warp,
//   wmax = reduce_max(ordered(val));  widx = reduce_min(val==wmax ? idx : ~0)
// -> exact (max value, min index) = first-occurrence semantics, ~1/3 the
// critical-path cycles of the previous shfl-tree + serialized smem atomicMax
// (which cost 16 x 32cyc same-bank ATOMS + an extra barrier).

#define BVAL 16
#define KVAL 11
#define NBK  (BVAL * KVAL)          // 176
#define HVAL 128
#define WVAL 128
#define HW   (HVAL * WVAL)
#define CVAL 7
#define NTHREADS 512                // 16 warps; warp w owns rows [8w, 8w+8)
#define NWARPS   (NTHREADS / 32)

__device__ float        g_labelloss_scratch[NBK];
__device__ unsigned int g_labelloss_count = 0;

__device__ __forceinline__ unsigned int float_to_ordered(float f)
{
    unsigned int u = __float_as_uint(f);
    return (u & 0x80000000u) ? ~u : (u | 0x80000000u);  // monotone, >0 finite
}

__global__ __launch_bounds__(NTHREADS)
void labelloss_fused_kernel(const float* __restrict__ pred,
                            const float* __restrict__ gt,
                            const float* __restrict__ heatmap,
                            float* __restrict__ out)
{
    const int bk   = blockIdx.x;            // b*K + k
    const int tid  = threadIdx.x;
    const int lane = tid & 31;
    const int warp = tid >> 5;              // 0..15
    const int x0   = warp * 8;              // row strip start
    const int c0   = lane * 4;              // 4 columns per lane

    __shared__ unsigned int swv[NWARPS];    // per-warp ordered max value
    __shared__ unsigned int swi[NWARPS];    // per-warp min index at that value

    const float* __restrict__ hm = heatmap + (size_t)bk * HW;

    // ---- Phase 1: front-batch all loads (rows x0-1 .. x0+8) -> MLP = 10 ----
    float4 v[10];
    #pragma unroll
    for (int i = 0; i < 10; ++i) {
        const int x = x0 - 1 + i;
        if ((unsigned)x < (unsigned)HVAL) {
            v[i] = *reinterpret_cast<const float4*>(hm + x * WVAL + c0);
        } else {
            v[i] = make_float4(0.f, 0.f, 0.f, 0.f);
        }
    }

    // ---- Phase 2: vertical 3-tap first (thread-local, no communication) ----
    float4 cs[8];
    #pragma unroll
    for (int j = 0; j < 8; ++j) {
        cs[j].x = v[j].x + v[j + 1].x + v[j + 2].x;
        cs[j].y = v[j].y + v[j + 1].y + v[j + 2].y;
        cs[j].z = v[j].z + v[j + 1].z + v[j + 2].z;
        cs[j].w = v[j].w + v[j + 1].w + v[j + 2].w;
    }

    // ---- Phase 3: horizontal 3-tap per output row (2 shuffles) + argmax ----
    float best = -FLT_MAX;
    int   bidx = 0x7FFFFFFF;
    #pragma unroll
    for (int j = 0; j < 8; ++j) {
        float left  = __shfl_up_sync(0xffffffffu, cs[j].w, 1);
        float right = __shfl_down_sync(0xffffffffu, cs[j].x, 1);
        if (lane == 0)  left  = 0.f;        // column -1 pad
        if (lane == 31) right = 0.f;        // column 128 pad
        float p0 = left     + cs[j].x + cs[j].y;
        float p1 = cs[j].x  + cs[j].y + cs[j].z;
        float p2 = cs[j].y  + cs[j].z + cs[j].w;
        float p3 = cs[j].z  + cs[j].w + right;
        const int base = (x0 + j) * WVAL + c0;
        // ascending index + strict '>' preserves first-occurrence semantics
        if (p0 > best) { best = p0; bidx = base;     }
        if (p1 > best) { best = p1; bidx = base + 1; }
        if (p2 > best) { best = p2; bidx = base + 2; }
        if (p3 > best) { best = p3; bidx = base + 3; }
    }

    // ---- Phase 4: warp argmax via HW redux, store to per-warp slot ----
    {
        const unsigned ov   = float_to_ordered(best);
        const unsigned wmax = __reduce_max_sync(0xffffffffu, ov);
        const unsigned cand = (ov == wmax) ? (unsigned)bidx : 0xFFFFFFFFu;
        const unsigned widx = __reduce_min_sync(0xffffffffu, cand);
        if (lane == 0) { swv[warp] = wmax; swi[warp] = widx; }
    }
    __syncthreads();                         // all 16 slots visible

    // ---- Phase 5: warp 0 reduces the 16 slots, gathers, counts ----
    if (warp == 0) {
        const unsigned ov2  = (lane < NWARPS) ? swv[lane] : 0u;
        const unsigned ix2  = (lane < NWARPS) ? swi[lane] : 0xFFFFFFFFu;
        const unsigned cmax = __reduce_max_sync(0xffffffffu, ov2);
        const unsigned c2   = (ov2 == cmax) ? ix2 : 0xFFFFFFFFu;
        const unsigned idx  = __reduce_min_sync(0xffffffffu, c2);  // all lanes

        unsigned cnt = 0;
        if (lane == 0) {
            const float* __restrict__ pk = pred + (size_t)bk * CVAL * HW;
            const float* __restrict__ g  = gt   + (size_t)bk * CVAL;
            float loss = 0.0f;
            #pragma unroll
            for (int c = 0; c < CVAL; ++c) { // 7 independent loads, MLP=7
                float d = pk[c * HW + idx] - g[c];
                loss = fmaf(d, d, loss);
            }
            g_labelloss_scratch[bk] = loss;
            __threadfence();                 // scratch visible before count
            cnt = atomicAdd(&g_labelloss_count, 1u);
        }
        cnt = __shfl_sync(0xffffffffu, cnt, 0);

        if (cnt == NBK - 1) {                // last CTA: final mean
            __threadfence();                 // acquire all scratch writes
            if (lane < BVAL) {
                float s = 0.0f;
                #pragma unroll
                for (int k = 0; k < KVAL; ++k)           // fixed order, MLP=11
                    s += g_labelloss_scratch[lane * KVAL + k];
                out[lane] = s * (1.0f / (float)KVAL);
            }
            if (lane == 0) g_labelloss_count = 0;        // reset for next replay
        }
    }
}

extern "C" void kernel_launch(void* const* d_in, const int* in_sizes, int n_in,
                              void* d_out, int out_size)
{
    const float* pred    = (const float*)d_in[0];
    const float* gt      = (const float*)d_in[1];
    const float* heatmap = (const float*)d_in[2];
    float* out = (float*)d_out;

    labelloss_fused_kernel<<<NBK, NTHREADS>>>(pred, gt, heatmap, out);
}

// round 17
// speedup vs baseline: 1.2657x; 1.0037x over previous
#include <cuda_runtime.h>
#include <cuda_bf16.h>
#include <float.h>

// LabelLoss: B=16, K=11, H=W=128, C=7 — single fused kernel.
//   pooled = 3x3 box-sum (pad 1) of heatmap[b,k]  (÷9 dropped: argmax-invariant)
//   idx    = argmax over flattened HxW (first occurrence)
//   loss[b,k] = sum_c (pred[b, k*7+c, idx/W, idx%W] - gt[b,k,c])^2
//   out[b] = mean_k loss[b,k]   (last CTA to finish)
//
// One CTA per (b,k): 176 CTAs x 512 threads (all co-resident, 2 CTAs/SM).
// Argmax via redux.sync HW reduce (max value, then min index among ties ->
// exact first-occurrence). NEW: the final idx is always one of the 16
// per-warp winners, so each warp speculatively L2-prefetches the 7 pred
// gather lines for ITS winner before the barrier — the winning CTA-level
// gather then hits L2 instead of paying a cold DRAM round on the serial tail.

#define BVAL 16
#define KVAL 11
#define NBK  (BVAL * KVAL)          // 176
#define HVAL 128
#define WVAL 128
#define HW   (HVAL * WVAL)
#define CVAL 7
#define NTHREADS 512                // 16 warps; warp w owns rows [8w, 8w+8)
#define NWARPS   (NTHREADS / 32)

__device__ float        g_labelloss_scratch[NBK];
__device__ unsigned int g_labelloss_count = 0;

__device__ __forceinline__ unsigned int float_to_ordered(float f)
{
    unsigned int u = __float_as_uint(f);
    return (u & 0x80000000u) ? ~u : (u | 0x80000000u);  // monotone, >0 finite
}

__global__ __launch_bounds__(NTHREADS)
void labelloss_fused_kernel(const float* __restrict__ pred,
                            const float* __restrict__ gt,
                            const float* __restrict__ heatmap,
                            float* __restrict__ out)
{
    const int bk   = blockIdx.x;            // b*K + k
    const int tid  = threadIdx.x;
    const int lane = tid & 31;
    const int warp = tid >> 5;              // 0..15
    const int x0   = warp * 8;              // row strip start
    const int c0   = lane * 4;              // 4 columns per lane

    __shared__ unsigned int swv[NWARPS];    // per-warp ordered max value
    __shared__ unsigned int swi[NWARPS];    // per-warp min index at that value

    const float* __restrict__ hm = heatmap + (size_t)bk * HW;
    const float* __restrict__ pk = pred + (size_t)bk * CVAL * HW;

    // ---- Phase 1: front-batch all loads (rows x0-1 .. x0+8) -> MLP = 10 ----
    float4 v[10];
    #pragma unroll
    for (int i = 0; i < 10; ++i) {
        const int x = x0 - 1 + i;
        if ((unsigned)x < (unsigned)HVAL) {
            v[i] = *reinterpret_cast<const float4*>(hm + x * WVAL + c0);
        } else {
            v[i] = make_float4(0.f, 0.f, 0.f, 0.f);
        }
    }

    // ---- Phase 2: vertical 3-tap first (thread-local, no communication) ----
    float4 cs[8];
    #pragma unroll
    for (int j = 0; j < 8; ++j) {
        cs[j].x = v[j].x + v[j + 1].x + v[j + 2].x;
        cs[j].y = v[j].y + v[j + 1].y + v[j + 2].y;
        cs[j].z = v[j].z + v[j + 1].z + v[j + 2].z;
        cs[j].w = v[j].w + v[j + 1].w + v[j + 2].w;
    }

    // ---- Phase 3: horizontal 3-tap per output row (2 shuffles) + argmax ----
    float best = -FLT_MAX;
    int   bidx = 0x7FFFFFFF;
    #pragma unroll
    for (int j = 0; j < 8; ++j) {
        float left  = __shfl_up_sync(0xffffffffu, cs[j].w, 1);
        float right = __shfl_down_sync(0xffffffffu, cs[j].x, 1);
        if (lane == 0)  left  = 0.f;        // column -1 pad
        if (lane == 31) right = 0.f;        // column 128 pad
        float p0 = left     + cs[j].x + cs[j].y;
        float p1 = cs[j].x  + cs[j].y + cs[j].z;
        float p2 = cs[j].y  + cs[j].z + cs[j].w;
        float p3 = cs[j].z  + cs[j].w + right;
        const int base = (x0 + j) * WVAL + c0;
        // ascending index + strict '>' preserves first-occurrence semantics
        if (p0 > best) { best = p0; bidx = base;     }
        if (p1 > best) { best = p1; bidx = base + 1; }
        if (p2 > best) { best = p2; bidx = base + 2; }
        if (p3 > best) { best = p3; bidx = base + 3; }
    }

    // ---- Phase 4: warp argmax via HW redux + speculative pred prefetch ----
    {
        const unsigned ov   = float_to_ordered(best);
        const unsigned wmax = __reduce_max_sync(0xffffffffu, ov);
        const unsigned cand = (ov == wmax) ? (unsigned)bidx : 0xFFFFFFFFu;
        const unsigned widx = __reduce_min_sync(0xffffffffu, cand);
        if (lane == 0) { swv[warp] = wmax; swi[warp] = widx; }

        // Final idx is one of the 16 warp winners: warm L2 for this warp's
        // candidate gather lines now (lanes 0..6, one channel each; pure
        // hint, off the dependency chain, issued ~300cyc before the gather).
        if (lane < CVAL) {
            const float* p = pk + (size_t)lane * HW + widx;
            asm volatile("prefetch.global.L2 [%0];" :: "l"(p));
        }
    }
    __syncthreads();                         // all 16 slots visible

    // ---- Phase 5: warp 0 reduces the 16 slots, gathers, counts ----
    if (warp == 0) {
        const unsigned ov2  = (lane < NWARPS) ? swv[lane] : 0u;
        const unsigned ix2  = (lane < NWARPS) ? swi[lane] : 0xFFFFFFFFu;
        const unsigned cmax = __reduce_max_sync(0xffffffffu, ov2);
        const unsigned c2   = (ov2 == cmax) ? ix2 : 0xFFFFFFFFu;
        const unsigned idx  = __reduce_min_sync(0xffffffffu, c2);  // all lanes

        unsigned cnt = 0;
        if (lane == 0) {
            const float* __restrict__ g = gt + (size_t)bk * CVAL;
            float loss = 0.0f;
            #pragma unroll
            for (int c = 0; c < CVAL; ++c) { // 7 loads, MLP=7, L2-warmed
                float d = pk[c * HW + idx] - g[c];
                loss = fmaf(d, d, loss);
            }
            g_labelloss_scratch[bk] = loss;
            __threadfence();                 // scratch visible before count
            cnt = atomicAdd(&g_labelloss_count, 1u);
        }
        cnt = __shfl_sync(0xffffffffu, cnt, 0);

        if (cnt == NBK - 1) {                // last CTA: final mean
            __threadfence();                 // acquire all scratch writes
            if (lane < BVAL) {
                float s = 0.0f;
                #pragma unroll
                for (int k = 0; k < KVAL; ++k)           // fixed order, MLP=11
                    s += g_labelloss_scratch[lane * KVAL + k];
                out[lane] = s * (1.0f / (float)KVAL);
            }
            if (lane == 0) g_labelloss_count = 0;        // reset for next replay
        }
    }
}

extern "C" void kernel_launch(void* const* d_in, const int* in_sizes, int n_in,
                              void* d_out, int out_size)
{
    const float* pred    = (const float*)d_in[0];
    const float* gt      = (const float*)d_in[1];
    const float* heatmap = (const float*)d_in[2];
    float* out = (float*)d_out;

    labelloss_fused_kernel<<<NBK, NTHREADS>>>(pred, gt, heatmap, out);
}